// round 1
// baseline (speedup 1.0000x reference)
#include <cuda_runtime.h>
#include <math.h>

#define N_NODES 2000
#define NFEAT   128
#define LB      128
#define TFEAT   36
#define FC1     256
#define DELTA_MIN 0.05f

// ---------------- scratch (device globals; no allocation) ----------------
__device__ float g_accP[8][FC1 * LB];      // split-K partials of spatial hidden, [split][k][t]
__device__ float g_HsT[FC1 * LB];          // relu spatial hidden, [k][t]
__device__ float g_HtT[FC1 * LB];          // relu temporal hidden, [k][t]
__device__ float g_U1[N_NODES * LB];       // U[:,:,i1]  [n][t]
__device__ float g_U2[N_NODES * LB];       // U[:,:,i2]  [n][t]
__device__ float g_P [N_NODES * LB];       // U2 @ B^T   [m][f]

// ---------------- kernel 1: spatial hidden, split-K -----------------------
// grid (16 k-tiles of 16, 8 j-splits of 250), block 128 (t)
__global__ void k_hid_s(const float* __restrict__ li, const float* __restrict__ Ws1) {
    const int k0 = blockIdx.x * 16;
    const int j0 = blockIdx.y * 250;
    const int t  = threadIdx.x;

    __shared__ float smLi[25 * 128];   // [jj][t]
    __shared__ float smW [25 * 16];    // [jj][kk]

    float acc[16];
#pragma unroll
    for (int i = 0; i < 16; i++) acc[i] = 0.f;

    for (int jb = 0; jb < 250; jb += 25) {
        __syncthreads();
#pragma unroll
        for (int i = 0; i < 25; i++)
            smLi[i * 128 + t] = li[t * N_NODES + j0 + jb + i];
        for (int e = t; e < 25 * 16; e += 128) {
            int jj = e >> 4, kk = e & 15;
            smW[e] = Ws1[(j0 + jb + jj) * FC1 + k0 + kk];
        }
        __syncthreads();
#pragma unroll
        for (int jj = 0; jj < 25; jj++) {
            float a = smLi[jj * 128 + t];
            const float4* w4 = (const float4*)&smW[jj * 16];
#pragma unroll
            for (int q = 0; q < 4; q++) {
                float4 w = w4[q];
                acc[q*4+0] += a * w.x; acc[q*4+1] += a * w.y;
                acc[q*4+2] += a * w.z; acc[q*4+3] += a * w.w;
            }
        }
    }
#pragma unroll
    for (int kk = 0; kk < 16; kk++)
        g_accP[blockIdx.y][(k0 + kk) * 128 + t] = acc[kk];
}

// ---------------- kernel 2: finalize spatial + full temporal hidden -------
// grid 256 (k), block 128 (t)
__global__ void k_hid_fin(const float* __restrict__ tf, const float* __restrict__ Wt1,
                          const float* __restrict__ bs1, const float* __restrict__ bt1) {
    const int k = blockIdx.x;
    const int t = threadIdx.x;
    float hs = bs1[k];
#pragma unroll
    for (int s = 0; s < 8; s++) hs += g_accP[s][k * 128 + t];
    g_HsT[k * 128 + t] = fmaxf(hs, 0.f);

    float a = bt1[k];
#pragma unroll
    for (int j = 0; j < TFEAT; j++)
        a += tf[t * TFEAT + j] * Wt1[j * FC1 + k];
    g_HtT[k * 128 + t] = fmaxf(a, 0.f);
}

// ---------------- kernel 3: gathered-column second layer -> U1,U2 ---------
// grid 250 (8 nodes each), block 256 = (t 0..127) x (col-half h 0..1)
__global__ __launch_bounds__(256) void k_embed(
    const float* __restrict__ Ws2, const float* __restrict__ bs2,
    const float* __restrict__ Wt2, const float* __restrict__ bt2,
    const int* __restrict__ idxp, const int* __restrict__ tdp) {

    __shared__ float smWs[256 * 16];   // [k][col]
    __shared__ float smWt[256 * 16];
    __shared__ float smBs[16], smBt[16];

    const int idx = idxp[0];
    const int td  = tdp[0];
    const int i1  = (td >= 0) ? (idx - td) : idx;
    const int i2  = (td >= 0) ? idx        : (idx + td);

    const int n0  = blockIdx.x * 8;
    const int tid = threadIdx.x;

    for (int e = tid; e < 256 * 16; e += 256) {
        int k = e >> 4, cc = e & 15;
        int n = n0 + (cc >> 1);
        int c = n * NFEAT + ((cc & 1) ? i2 : i1);
        smWs[e] = Ws2[(long)k * (N_NODES * NFEAT) + c];
        smWt[e] = Wt2[(long)k * (N_NODES * NFEAT) + c];
    }
    if (tid < 16) {
        int n = n0 + (tid >> 1);
        int c = n * NFEAT + ((tid & 1) ? i2 : i1);
        smBs[tid] = bs2[c];
        smBt[tid] = bt2[c];
    }
    __syncthreads();

    const int t = tid & 127;
    const int h = tid >> 7;   // cols h*8 .. h*8+7

    float accS[8], accT[8];
#pragma unroll
    for (int i = 0; i < 8; i++) { accS[i] = 0.f; accT[i] = 0.f; }

    for (int k = 0; k < 256; k++) {
        float hs = g_HsT[k * 128 + t];
        float ht = g_HtT[k * 128 + t];
        float4 a0 = *(const float4*)&smWs[k * 16 + h * 8];
        float4 a1 = *(const float4*)&smWs[k * 16 + h * 8 + 4];
        float4 b0 = *(const float4*)&smWt[k * 16 + h * 8];
        float4 b1 = *(const float4*)&smWt[k * 16 + h * 8 + 4];
        accS[0] += hs * a0.x; accS[1] += hs * a0.y; accS[2] += hs * a0.z; accS[3] += hs * a0.w;
        accS[4] += hs * a1.x; accS[5] += hs * a1.y; accS[6] += hs * a1.z; accS[7] += hs * a1.w;
        accT[0] += ht * b0.x; accT[1] += ht * b0.y; accT[2] += ht * b0.z; accT[3] += ht * b0.w;
        accT[4] += ht * b1.x; accT[5] += ht * b1.y; accT[6] += ht * b1.z; accT[7] += ht * b1.w;
    }

#pragma unroll
    for (int i = 0; i < 8; i++) {
        int col = h * 8 + i;
        float v = fmaxf(accS[i] + smBs[col], 0.f) + fmaxf(accT[i] + smBt[col], 0.f);
        int n = n0 + (col >> 1);
        if (col & 1) g_U2[n * 128 + t] = v;
        else         g_U1[n * 128 + t] = v;
    }
}

// ---------------- kernel 4: P = U2 @ B^T ----------------------------------
// grid 250 (8 rows each), block 128 (f)
__global__ void k_u2b(const float* __restrict__ B) {
    __shared__ float smU2[8 * 128];   // [mm][g]
    const int m0 = blockIdx.x * 8;
    const int f  = threadIdx.x;
    for (int e = f; e < 8 * 128; e += 128) smU2[e] = g_U2[m0 * 128 + e];
    __syncthreads();

    float acc[8];
#pragma unroll
    for (int i = 0; i < 8; i++) acc[i] = 0.f;
#pragma unroll 8
    for (int g4 = 0; g4 < 128; g4 += 4) {
        float4 b = *(const float4*)&B[f * 128 + g4];
#pragma unroll
        for (int mm = 0; mm < 8; mm++) {
            float4 u = *(const float4*)&smU2[mm * 128 + g4];
            acc[mm] += u.x * b.x + u.y * b.y + u.z * b.z + u.w * b.w;
        }
    }
#pragma unroll
    for (int mm = 0; mm < 8; mm++)
        g_P[(m0 + mm) * 128 + f] = acc[mm];
}

// ---------------- kernel 5: x = U1 @ P^T with threshold -------------------
// grid (16,16) tiles of 128x128, block 256, thread tile 8x8, K=128 in 4 chunks
__global__ __launch_bounds__(256) void k_gemm(float* __restrict__ out) {
    __shared__ float smA[32 * 132];   // [k][row], pad 132
    __shared__ float smB[32 * 132];   // [k][col]
    const int n0  = blockIdx.y * 128;
    const int m0  = blockIdx.x * 128;
    const int tid = threadIdx.x;
    const int tx  = tid & 15, ty = tid >> 4;

    float acc[8][8];
#pragma unroll
    for (int i = 0; i < 8; i++)
#pragma unroll
        for (int j = 0; j < 8; j++) acc[i][j] = 0.f;

    for (int kc = 0; kc < 128; kc += 32) {
        __syncthreads();
        for (int e = tid; e < 128 * 32; e += 256) {
            int row = e >> 5, kk = e & 31;
            int n = n0 + row;
            int m = m0 + row;
            smA[kk * 132 + row] = (n < N_NODES) ? g_U1[n * 128 + kc + kk] : 0.f;
            smB[kk * 132 + row] = (m < N_NODES) ? g_P [m * 128 + kc + kk] : 0.f;
        }
        __syncthreads();
#pragma unroll
        for (int k = 0; k < 32; k++) {
            float4 a0 = *(const float4*)&smA[k * 132 + ty * 8];
            float4 a1 = *(const float4*)&smA[k * 132 + ty * 8 + 4];
            float4 b0 = *(const float4*)&smB[k * 132 + tx * 8];
            float4 b1 = *(const float4*)&smB[k * 132 + tx * 8 + 4];
            float av[8] = {a0.x,a0.y,a0.z,a0.w,a1.x,a1.y,a1.z,a1.w};
            float bv[8] = {b0.x,b0.y,b0.z,b0.w,b1.x,b1.y,b1.z,b1.w};
#pragma unroll
            for (int i = 0; i < 8; i++)
#pragma unroll
                for (int j = 0; j < 8; j++)
                    acc[i][j] += av[i] * bv[j];
        }
    }

#pragma unroll
    for (int i = 0; i < 8; i++) {
        int n = n0 + ty * 8 + i;
        if (n >= N_NODES) continue;
#pragma unroll
        for (int jq = 0; jq < 2; jq++) {
            int m = m0 + tx * 8 + jq * 4;
            float4 v;
            v.x = acc[i][jq*4+0]; v.y = acc[i][jq*4+1];
            v.z = acc[i][jq*4+2]; v.w = acc[i][jq*4+3];
            v.x = (v.x >= DELTA_MIN) ? v.x : 0.f;
            v.y = (v.y >= DELTA_MIN) ? v.y : 0.f;
            v.z = (v.z >= DELTA_MIN) ? v.z : 0.f;
            v.w = (v.w >= DELTA_MIN) ? v.w : 0.f;
            if (m + 3 < N_NODES) {
                *(float4*)&out[(long)n * N_NODES + m] = v;
            } else {
                float tmp[4] = {v.x, v.y, v.z, v.w};
                for (int j = 0; j < 4; j++)
                    if (m + j < N_NODES) out[(long)n * N_NODES + m + j] = tmp[j];
            }
        }
    }
}

// ---------------- kernel 6: in-place row softmax --------------------------
// grid 2000 (row), block 256, 8 elems/thread
__global__ void k_softmax(float* __restrict__ out) {
    const int row = blockIdx.x;
    float* p = out + (long)row * N_NODES;
    const int tid = threadIdx.x;
    __shared__ float redM[8];
    __shared__ float redS[8];

    float v[8];
    float mx = -1e30f;
#pragma unroll
    for (int i = 0; i < 8; i++) {
        int c = tid + i * 256;
        v[i] = (c < N_NODES) ? p[c] : -1e30f;
        mx = fmaxf(mx, v[i]);
    }
#pragma unroll
    for (int o = 16; o; o >>= 1) mx = fmaxf(mx, __shfl_xor_sync(0xFFFFFFFFu, mx, o));
    if ((tid & 31) == 0) redM[tid >> 5] = mx;
    __syncthreads();
    float gmax = redM[0];
#pragma unroll
    for (int w = 1; w < 8; w++) gmax = fmaxf(gmax, redM[w]);

    float e[8];
    float s = 0.f;
#pragma unroll
    for (int i = 0; i < 8; i++) {
        int c = tid + i * 256;
        if (c < N_NODES) { e[i] = expf(v[i] - gmax); s += e[i]; }
        else e[i] = 0.f;
    }
#pragma unroll
    for (int o = 16; o; o >>= 1) s += __shfl_xor_sync(0xFFFFFFFFu, s, o);
    if ((tid & 31) == 0) redS[tid >> 5] = s;
    __syncthreads();
    float tot = 0.f;
#pragma unroll
    for (int w = 0; w < 8; w++) tot += redS[w];
    float inv = 1.f / tot;
#pragma unroll
    for (int i = 0; i < 8; i++) {
        int c = tid + i * 256;
        if (c < N_NODES) p[c] = e[i] * inv;
    }
}

// ---------------- launch ---------------------------------------------------
extern "C" void kernel_launch(void* const* d_in, const int* in_sizes, int n_in,
                              void* d_out, int out_size) {
    const float* tf   = (const float*)d_in[0];
    const float* li   = (const float*)d_in[1];
    const float* Ws1  = (const float*)d_in[2];
    const float* bs1  = (const float*)d_in[3];
    const float* Ws2  = (const float*)d_in[4];
    const float* bs2  = (const float*)d_in[5];
    const float* Wt1  = (const float*)d_in[6];
    const float* bt1  = (const float*)d_in[7];
    const float* Wt2  = (const float*)d_in[8];
    const float* bt2  = (const float*)d_in[9];
    const float* B    = (const float*)d_in[10];
    const int*   idxp = (const int*)d_in[11];
    const int*   tdp  = (const int*)d_in[12];
    float* out = (float*)d_out;

    k_hid_s  <<<dim3(16, 8), 128>>>(li, Ws1);
    k_hid_fin<<<256, 128>>>(tf, Wt1, bs1, bt1);
    k_embed  <<<250, 256>>>(Ws2, bs2, Wt2, bt2, idxp, tdp);
    k_u2b    <<<250, 128>>>(B);
    k_gemm   <<<dim3(16, 16), 256>>>(out);
    k_softmax<<<2000, 256>>>(out);
}

// round 2
// speedup vs baseline: 1.4617x; 1.4617x over previous
#include <cuda_runtime.h>
#include <math.h>
#include <stdint.h>

#define N_NODES 2000
#define NFEAT   128
#define LB      128
#define TFEAT   36
#define FC1     256
#define DELTA_MIN 0.05f

// ---------------- scratch (device globals; no allocation) ----------------
__device__ float g_accP[25][FC1 * LB];     // split-K partials, layout [split][t*256 + k]
__device__ float g_HsT[FC1 * LB];          // relu spatial hidden, [k][t]
__device__ float g_HtT[FC1 * LB];          // relu temporal hidden, [k][t]
__device__ float g_U1[N_NODES * LB];       // U[:,:,i1]  [n][t]  (tf32-rounded)
__device__ float g_U2[N_NODES * LB];       // U[:,:,i2]  [n][t]  (full fp32)
__device__ float g_P [N_NODES * LB];       // U2 @ B^T   [m][f]  (tf32-rounded)

__device__ __forceinline__ float to_tf32(float x) {
    uint32_t u;
    asm("cvt.rna.tf32.f32 %0, %1;" : "=r"(u) : "f"(x));
    return __uint_as_float(u);
}

// ---------------- kernel 1: spatial hidden, split-K, coalesced ------------
// grid (4 k-tiles of 64, 25 j-splits of 80), block 256
__global__ __launch_bounds__(256) void k_hid_s(const float* __restrict__ li,
                                               const float* __restrict__ Ws1) {
    __shared__ float smA[16 * 132];   // [jj][t], pad 132
    __shared__ float smW[16 * 68];    // [jj][kk], pad 68
    const int k0 = blockIdx.x * 64;
    const int j0 = blockIdx.y * 80;
    const int tid = threadIdx.x;
    const int tx = tid & 15;          // k-group (4 cols each)
    const int ty = tid >> 4;          // t-group (8 rows each)

    float acc[8][4];
#pragma unroll
    for (int u = 0; u < 8; u++)
#pragma unroll
        for (int v = 0; v < 4; v++) acc[u][v] = 0.f;

    for (int jb = 0; jb < 80; jb += 16) {
        __syncthreads();
#pragma unroll
        for (int it = 0; it < 8; it++) {
            int e = tid + it * 256;
            int t = e >> 4, jj = e & 15;
            smA[jj * 132 + t] = li[t * N_NODES + j0 + jb + jj];
        }
#pragma unroll
        for (int it = 0; it < 4; it++) {
            int e = tid + it * 256;
            int jj = e >> 6, kk = e & 63;
            smW[jj * 68 + kk] = Ws1[(j0 + jb + jj) * FC1 + k0 + kk];
        }
        __syncthreads();
#pragma unroll
        for (int jj = 0; jj < 16; jj++) {
            float4 a0 = *(const float4*)&smA[jj * 132 + ty * 8];
            float4 a1 = *(const float4*)&smA[jj * 132 + ty * 8 + 4];
            float4 b  = *(const float4*)&smW[jj * 68 + tx * 4];
            float av[8] = {a0.x, a0.y, a0.z, a0.w, a1.x, a1.y, a1.z, a1.w};
            float bv[4] = {b.x, b.y, b.z, b.w};
#pragma unroll
            for (int u = 0; u < 8; u++)
#pragma unroll
                for (int v = 0; v < 4; v++) acc[u][v] += av[u] * bv[v];
        }
    }
    // store partials: [split][t*256 + k], float4 coalesced along k
    const int sp = blockIdx.y;
#pragma unroll
    for (int u = 0; u < 8; u++) {
        int t = ty * 8 + u;
        float4 v = make_float4(acc[u][0], acc[u][1], acc[u][2], acc[u][3]);
        *(float4*)&g_accP[sp][t * FC1 + k0 + tx * 4] = v;
    }
}

// ---------------- kernel 2: finalize spatial + temporal hidden ------------
// grid 128 (t), block 256 (k)
__global__ void k_hid_fin(const float* __restrict__ tf, const float* __restrict__ Wt1,
                          const float* __restrict__ bs1, const float* __restrict__ bt1) {
    const int t = blockIdx.x;
    const int k = threadIdx.x;
    __shared__ float stf[TFEAT];
    if (k < TFEAT) stf[k] = tf[t * TFEAT + k];

    float hs = bs1[k];
#pragma unroll
    for (int s = 0; s < 25; s++) hs += g_accP[s][t * FC1 + k];
    g_HsT[k * 128 + t] = fmaxf(hs, 0.f);

    __syncthreads();
    float a = bt1[k];
#pragma unroll
    for (int j = 0; j < TFEAT; j++)
        a += stf[j] * Wt1[j * FC1 + k];
    g_HtT[k * 128 + t] = fmaxf(a, 0.f);
}

// ---------------- kernel 3: gathered-column second layer -> U1,U2 ---------
// grid 250 (8 nodes each), block 256 = (t 0..127) x (col-half h 0..1)
__global__ __launch_bounds__(256) void k_embed(
    const float* __restrict__ Ws2, const float* __restrict__ bs2,
    const float* __restrict__ Wt2, const float* __restrict__ bt2,
    const int* __restrict__ idxp, const int* __restrict__ tdp) {

    __shared__ float smWs[256 * 16];   // [k][col]
    __shared__ float smWt[256 * 16];
    __shared__ float smBs[16], smBt[16];

    const int idx = idxp[0];
    const int td  = tdp[0];
    const int i1  = (td >= 0) ? (idx - td) : idx;
    const int i2  = (td >= 0) ? idx        : (idx + td);

    const int n0  = blockIdx.x * 8;
    const int tid = threadIdx.x;

    for (int e = tid; e < 256 * 16; e += 256) {
        int k = e >> 4, cc = e & 15;
        int n = n0 + (cc >> 1);
        int c = n * NFEAT + ((cc & 1) ? i2 : i1);
        smWs[e] = Ws2[(long)k * (N_NODES * NFEAT) + c];
        smWt[e] = Wt2[(long)k * (N_NODES * NFEAT) + c];
    }
    if (tid < 16) {
        int n = n0 + (tid >> 1);
        int c = n * NFEAT + ((tid & 1) ? i2 : i1);
        smBs[tid] = bs2[c];
        smBt[tid] = bt2[c];
    }
    __syncthreads();

    const int t = tid & 127;
    const int h = tid >> 7;   // cols h*8 .. h*8+7

    float accS[8], accT[8];
#pragma unroll
    for (int i = 0; i < 8; i++) { accS[i] = 0.f; accT[i] = 0.f; }

    for (int k = 0; k < 256; k++) {
        float hs = g_HsT[k * 128 + t];
        float ht = g_HtT[k * 128 + t];
        float4 a0 = *(const float4*)&smWs[k * 16 + h * 8];
        float4 a1 = *(const float4*)&smWs[k * 16 + h * 8 + 4];
        float4 b0 = *(const float4*)&smWt[k * 16 + h * 8];
        float4 b1 = *(const float4*)&smWt[k * 16 + h * 8 + 4];
        accS[0] += hs * a0.x; accS[1] += hs * a0.y; accS[2] += hs * a0.z; accS[3] += hs * a0.w;
        accS[4] += hs * a1.x; accS[5] += hs * a1.y; accS[6] += hs * a1.z; accS[7] += hs * a1.w;
        accT[0] += ht * b0.x; accT[1] += ht * b0.y; accT[2] += ht * b0.z; accT[3] += ht * b0.w;
        accT[4] += ht * b1.x; accT[5] += ht * b1.y; accT[6] += ht * b1.z; accT[7] += ht * b1.w;
    }

#pragma unroll
    for (int i = 0; i < 8; i++) {
        int col = h * 8 + i;
        float v = fmaxf(accS[i] + smBs[col], 0.f) + fmaxf(accT[i] + smBt[col], 0.f);
        int n = n0 + (col >> 1);
        if (col & 1) g_U2[n * 128 + t] = v;            // full precision -> feeds P
        else         g_U1[n * 128 + t] = to_tf32(v);   // tf32-rounded  -> feeds mma A
    }
}

// ---------------- kernel 4: P = U2 @ B^T ----------------------------------
// grid 125 (16 rows each), block 128 (f)
__global__ __launch_bounds__(128) void k_u2b(const float* __restrict__ B) {
    __shared__ float smB[128 * 68];   // [f][g-chunk], pad 68
    __shared__ float smU[16 * 68];    // [mm][g-chunk]
    const int m0 = blockIdx.x * 16;
    const int tid = threadIdx.x;
    const int f = tid;

    float acc[16];
#pragma unroll
    for (int i = 0; i < 16; i++) acc[i] = 0.f;

    for (int gc = 0; gc < 128; gc += 64) {
        __syncthreads();
#pragma unroll
        for (int it = 0; it < 16; it++) {
            int e = tid + it * 128;
            int row = e >> 4, g4 = (e & 15) * 4;
            *(float4*)&smB[row * 68 + g4] = *(const float4*)&B[row * 128 + gc + g4];
        }
#pragma unroll
        for (int it = 0; it < 2; it++) {
            int e = tid + it * 128;
            int row = e >> 4, g4 = (e & 15) * 4;
            *(float4*)&smU[row * 68 + g4] = *(const float4*)&g_U2[(m0 + row) * 128 + gc + g4];
        }
        __syncthreads();
#pragma unroll
        for (int g4 = 0; g4 < 64; g4 += 4) {
            float4 b = *(const float4*)&smB[f * 68 + g4];
#pragma unroll
            for (int mm = 0; mm < 16; mm++) {
                float4 u = *(const float4*)&smU[mm * 68 + g4];
                acc[mm] += u.x * b.x + u.y * b.y + u.z * b.z + u.w * b.w;
            }
        }
    }
#pragma unroll
    for (int mm = 0; mm < 16; mm++)
        g_P[(m0 + mm) * 128 + f] = to_tf32(acc[mm]);
}

// ---------------- kernel 5: x = U1 @ P^T (tf32 tensor cores) --------------
// grid (16,16) tiles of 128x128, block 256 (8 warps: 4 n-strips x 2 m-strips)
#define MMA_TF32(c, a, b)                                                          \
    asm volatile("mma.sync.aligned.m16n8k8.row.col.f32.tf32.tf32.f32 "             \
                 "{%0,%1,%2,%3},{%4,%5,%6,%7},{%8,%9},{%0,%1,%2,%3};"              \
                 : "+f"(c[0]), "+f"(c[1]), "+f"(c[2]), "+f"(c[3])                  \
                 : "r"(a[0]), "r"(a[1]), "r"(a[2]), "r"(a[3]), "r"(b[0]), "r"(b[1]))

__global__ __launch_bounds__(256) void k_gemm(float* __restrict__ out) {
    __shared__ float smA[128 * 36];   // [n][k-chunk 32], pad 36
    __shared__ float smB[128 * 36];   // [m][k-chunk 32], pad 36
    const int n0 = blockIdx.y * 128;
    const int m0 = blockIdx.x * 128;
    const int tid = threadIdx.x;
    const int warp = tid >> 5, lane = tid & 31;
    const int wn = warp & 3;          // n-strip of 32
    const int wm = warp >> 2;         // m-strip of 64
    const int g = lane >> 2, tg = lane & 3;

    float acc[2][8][4];
#pragma unroll
    for (int i = 0; i < 2; i++)
#pragma unroll
        for (int j = 0; j < 8; j++)
#pragma unroll
            for (int q = 0; q < 4; q++) acc[i][j][q] = 0.f;

    for (int kc = 0; kc < 128; kc += 32) {
        __syncthreads();
#pragma unroll
        for (int it = 0; it < 4; it++) {
            int q = tid + it * 256;
            int row = q >> 3, kk = (q & 7) * 4;
            float4 a = (n0 + row < N_NODES) ? *(const float4*)&g_U1[(n0 + row) * 128 + kc + kk]
                                            : make_float4(0, 0, 0, 0);
            float4 b = (m0 + row < N_NODES) ? *(const float4*)&g_P [(m0 + row) * 128 + kc + kk]
                                            : make_float4(0, 0, 0, 0);
            *(float4*)&smA[row * 36 + kk] = a;
            *(float4*)&smB[row * 36 + kk] = b;
        }
        __syncthreads();
#pragma unroll
        for (int ks = 0; ks < 4; ks++) {
            int k0 = ks * 8;
            uint32_t af[2][4];
#pragma unroll
            for (int i = 0; i < 2; i++) {
                int base = (wn * 32 + i * 16) * 36 + k0;
                af[i][0] = __float_as_uint(smA[base + g * 36 + tg]);
                af[i][1] = __float_as_uint(smA[base + (g + 8) * 36 + tg]);
                af[i][2] = __float_as_uint(smA[base + g * 36 + tg + 4]);
                af[i][3] = __float_as_uint(smA[base + (g + 8) * 36 + tg + 4]);
            }
            uint32_t bf[8][2];
#pragma unroll
            for (int j = 0; j < 8; j++) {
                int bb = (wm * 64 + j * 8 + g) * 36 + k0 + tg;
                bf[j][0] = __float_as_uint(smB[bb]);
                bf[j][1] = __float_as_uint(smB[bb + 4]);
            }
#pragma unroll
            for (int i = 0; i < 2; i++)
#pragma unroll
                for (int j = 0; j < 8; j++)
                    MMA_TF32(acc[i][j], af[i], bf[j]);
        }
    }

    // epilogue: threshold + store
#pragma unroll
    for (int i = 0; i < 2; i++) {
#pragma unroll
        for (int j = 0; j < 8; j++) {
            int n = n0 + wn * 32 + i * 16 + g;
            int m = m0 + wm * 64 + j * 8 + 2 * tg;
            if (m < N_NODES) {
                float2 v0, v1;
                v0.x = (acc[i][j][0] >= DELTA_MIN) ? acc[i][j][0] : 0.f;
                v0.y = (acc[i][j][1] >= DELTA_MIN) ? acc[i][j][1] : 0.f;
                v1.x = (acc[i][j][2] >= DELTA_MIN) ? acc[i][j][2] : 0.f;
                v1.y = (acc[i][j][3] >= DELTA_MIN) ? acc[i][j][3] : 0.f;
                if (n < N_NODES)     *(float2*)&out[(long)n * N_NODES + m] = v0;
                if (n + 8 < N_NODES) *(float2*)&out[(long)(n + 8) * N_NODES + m] = v1;
            }
        }
    }
}

// ---------------- kernel 6: in-place row softmax --------------------------
__global__ void k_softmax(float* __restrict__ out) {
    const int row = blockIdx.x;
    float* p = out + (long)row * N_NODES;
    const int tid = threadIdx.x;
    __shared__ float redM[8];
    __shared__ float redS[8];

    float v[8];
    float mx = -1e30f;
#pragma unroll
    for (int i = 0; i < 8; i++) {
        int c = tid + i * 256;
        v[i] = (c < N_NODES) ? p[c] : -1e30f;
        mx = fmaxf(mx, v[i]);
    }
#pragma unroll
    for (int o = 16; o; o >>= 1) mx = fmaxf(mx, __shfl_xor_sync(0xFFFFFFFFu, mx, o));
    if ((tid & 31) == 0) redM[tid >> 5] = mx;
    __syncthreads();
    float gmax = redM[0];
#pragma unroll
    for (int w = 1; w < 8; w++) gmax = fmaxf(gmax, redM[w]);

    float e[8];
    float s = 0.f;
#pragma unroll
    for (int i = 0; i < 8; i++) {
        int c = tid + i * 256;
        if (c < N_NODES) { e[i] = expf(v[i] - gmax); s += e[i]; }
        else e[i] = 0.f;
    }
#pragma unroll
    for (int o = 16; o; o >>= 1) s += __shfl_xor_sync(0xFFFFFFFFu, s, o);
    if ((tid & 31) == 0) redS[tid >> 5] = s;
    __syncthreads();
    float tot = 0.f;
#pragma unroll
    for (int w = 0; w < 8; w++) tot += redS[w];
    float inv = 1.f / tot;
#pragma unroll
    for (int i = 0; i < 8; i++) {
        int c = tid + i * 256;
        if (c < N_NODES) p[c] = e[i] * inv;
    }
}

// ---------------- launch ---------------------------------------------------
extern "C" void kernel_launch(void* const* d_in, const int* in_sizes, int n_in,
                              void* d_out, int out_size) {
    const float* tf   = (const float*)d_in[0];
    const float* li   = (const float*)d_in[1];
    const float* Ws1  = (const float*)d_in[2];
    const float* bs1  = (const float*)d_in[3];
    const float* Ws2  = (const float*)d_in[4];
    const float* bs2  = (const float*)d_in[5];
    const float* Wt1  = (const float*)d_in[6];
    const float* bt1  = (const float*)d_in[7];
    const float* Wt2  = (const float*)d_in[8];
    const float* bt2  = (const float*)d_in[9];
    const float* B    = (const float*)d_in[10];
    const int*   idxp = (const int*)d_in[11];
    const int*   tdp  = (const int*)d_in[12];
    float* out = (float*)d_out;

    k_hid_s  <<<dim3(4, 25), 256>>>(li, Ws1);
    k_hid_fin<<<128, 256>>>(tf, Wt1, bs1, bt1);
    k_embed  <<<250, 256>>>(Ws2, bs2, Wt2, bt2, idxp, tdp);
    k_u2b    <<<125, 128>>>(B);
    k_gemm   <<<dim3(16, 16), 256>>>(out);
    k_softmax<<<2000, 256>>>(out);
}